// round 14
// baseline (speedup 1.0000x reference)
#include <cuda_runtime.h>
#include <cuda_fp16.h>
#include <cstdint>

// out(4096,128) = input(4096,49998) @ word2vecs[0:49998](49998,128), fp32.
// fp16 m16n8k16 mma.sync path (same 11-bit significand as tf32 -> same error;
// tcgen05 unavailable: harness PTX target is compute_103, no 'a' features).
#define KDIM 49998
#define MDIM 4096
#define NDIM 128
#define KPAD 50048             // BT row stride in halves (zero-padded)
#define SPLITS 9
#define KSPLIT 5568            // 174*32 ; 9*5568 >= KDIM
#define BM 128
#define BK 32
#define STAGES 3
#define NTHREADS 256
#define RSH 40                 // fp16 smem row stride (halves); 80B = 16B-mult
#define B16_BYTES (BM * RSH * 2)            // 10240
#define A16_BYTES (BM * RSH * 2)            // 10240
#define SMEM_B16(s) ((s) * B16_BYTES)                    // 0 .. 30720
#define SMEM_A16(d) (3 * B16_BYTES + (d) * A16_BYTES)    // 30720 ..
#define SMEM_TOTAL  (SMEM_A16(2))                        // 51200 -> 2 CTAs/SM (reg-capped)

__device__ __half g_bt16[(size_t)NDIM * KPAD];           // B^T fp16, zero-padded
__device__ float  g_part[(size_t)SPLITS * MDIM * NDIM];  // split-K partials
__device__ int    g_cnt[MDIM / BM];                      // per-tile arrival counters

// ---------------- helpers ----------------
__device__ __forceinline__ uint32_t smem_u32(const void* p) {
    uint32_t a;
    asm("{ .reg .u64 t; cvta.to.shared.u64 t, %1; cvt.u32.u64 %0, t; }" : "=r"(a) : "l"(p));
    return a;
}
__device__ __forceinline__ void cp16(uint32_t dst, const void* src) {
    asm volatile("cp.async.cg.shared.global [%0], [%1], 16;" :: "r"(dst), "l"(src));
}
__device__ __forceinline__ void cp_commit() { asm volatile("cp.async.commit_group;" ::: "memory"); }
__device__ __forceinline__ void cp_wait1() { asm volatile("cp.async.wait_group 1;" ::: "memory"); }
__device__ __forceinline__ void cp_wait0() { asm volatile("cp.async.wait_group 0;" ::: "memory"); }

__device__ __forceinline__ uint32_t pack_h2(float hi, float lo) {
    uint32_t d;
    asm("cvt.rn.f16x2.f32 %0, %1, %2;" : "=r"(d) : "f"(hi), "f"(lo));
    return d;
}
__device__ __forceinline__ void ldsm4(uint32_t& r0, uint32_t& r1, uint32_t& r2, uint32_t& r3,
                                      uint32_t addr) {
    asm volatile("ldmatrix.sync.aligned.m8n8.x4.shared.b16 {%0,%1,%2,%3}, [%4];"
                 : "=r"(r0), "=r"(r1), "=r"(r2), "=r"(r3) : "r"(addr));
}
__device__ __forceinline__ void mma_fp16(float* c, const uint32_t* a, uint32_t b0, uint32_t b1) {
    asm volatile(
        "mma.sync.aligned.m16n8k16.row.col.f32.f16.f16.f32 "
        "{%0,%1,%2,%3}, {%4,%5,%6,%7}, {%8,%9}, {%0,%1,%2,%3};"
        : "+f"(c[0]), "+f"(c[1]), "+f"(c[2]), "+f"(c[3])
        : "r"(a[0]), "r"(a[1]), "r"(a[2]), "r"(a[3]), "r"(b0), "r"(b1));
}

// ------- kernel 1: transpose + fp16-convert B -> g_bt16[n][k] zero-padded; reset counters -------
__global__ void prep_b(const float* __restrict__ w2v) {
    __shared__ float tile[32][33];
    int k0 = blockIdx.x * 32;
    int n0 = blockIdx.y * 32;
    int tx = threadIdx.x, ty = threadIdx.y;  // 32 x 8
#pragma unroll
    for (int i = 0; i < 32; i += 8) {
        int k = k0 + ty + i;
        float v = 0.f;
        if (k < KDIM) v = w2v[(size_t)k * NDIM + n0 + tx];
        tile[ty + i][tx] = v;
    }
    __syncthreads();
#pragma unroll
    for (int i = 0; i < 32; i += 8) {
        int n = n0 + ty + i;
        g_bt16[(size_t)n * KPAD + k0 + tx] = __float2half_rn(tile[tx][ty + i]);
    }
    if (blockIdx.x == 0 && blockIdx.y == 0) {
        int tid = ty * 32 + tx;
        if (tid < MDIM / BM) g_cnt[tid] = 0;
    }
}

// ------- kernel 2: fp16 mma.sync GEMM; A LDG->reg->cvt->STS; unroll-6; 1 barrier/iter -------
__global__ void __launch_bounds__(NTHREADS, 2) gemm_fp16(float* __restrict__ out,
                                                         const float* __restrict__ A) {
    extern __shared__ char smem[];
    const uint32_t sb = smem_u32(smem);
    const int tid = threadIdx.x;
    const int wid = tid >> 5, lane = tid & 31;
    const int lr = lane >> 2, lk = lane & 3;

    const int tile = blockIdx.x;
    const int m0 = tile * BM;
    const int split = blockIdx.y;
    const int klo = split * KSPLIT;
    const int khi = min(KDIM, klo + KSPLIT);
    const int iters = (khi - klo + BK - 1) / BK;   // 174 (171 on last split)

    const int wm = (wid & 1) * 64;   // warp M offset
    const int wc = (wid >> 1) * 32;  // warp N offset

    const uint32_t lm_off = ((uint32_t)(lane & 15) * RSH + (uint32_t)((lane >> 4) << 3)) * 2u;
    const uint32_t a_lm = sb + lm_off + (uint32_t)(wm * RSH * 2);  // + SMEM_A16(d)
    const uint32_t b_lm = sb + lm_off + (uint32_t)(wc * RSH * 2);  // + SMEM_B16(s)

    // ---- per-thread A slots (LDG direct; same thread converts what it loads) ----
    const float* a_base = A + (size_t)m0 * KDIM + klo;
    const int re = 2 * (tid >> 3), ge = tid & 7;                 // even rows: float4
    const uint32_t aoff_e = (uint32_t)re * KDIM + (uint32_t)ge * 4;
    const uint32_t d16_e = (uint32_t)(re * RSH + ge * 4) * 2u;
    const int ro = 2 * (tid >> 4) + 1, go = tid & 15;            // odd rows: float2
    const uint32_t aoff_o = (uint32_t)ro * KDIM + (uint32_t)go * 2;
    const uint32_t d16_o = (uint32_t)(ro * RSH + go * 2) * 2u;
    // B cp16 slots
    const int nb = tid >> 2, gb = tid & 3;
    const uint32_t boff = (uint32_t)nb * KPAD + (uint32_t)gb * 8;
    const uint32_t d_b = (uint32_t)(nb * RSH + gb * 8) * 2u;
    const __half* b_base = g_bt16 + klo;

    float4 ebuf[2];
    float2 obuf[4];

    float acc[4][4][4];
#pragma unroll
    for (int mi = 0; mi < 4; mi++)
#pragma unroll
        for (int ni = 0; ni < 4; ni++)
#pragma unroll
            for (int q = 0; q < 4; q++) acc[mi][ni][q] = 0.f;

    auto ldg_stage = [&](int koff) {
        if (klo + koff + BK <= khi) {
#pragma unroll
            for (int j = 0; j < 2; j++)
                ebuf[j] = __ldcg(reinterpret_cast<const float4*>(a_base + aoff_e + (uint32_t)j * 64u * KDIM + koff));
#pragma unroll
            for (int j = 0; j < 4; j++)
                obuf[j] = __ldcg(reinterpret_cast<const float2*>(a_base + aoff_o + (uint32_t)j * 32u * KDIM + koff));
        } else {
            const int kmax = khi - klo;
#pragma unroll
            for (int j = 0; j < 2; j++) {
                const float* s = a_base + aoff_e + (uint32_t)j * 64u * KDIM + koff;
                int k0 = koff + ge * 4;
                ebuf[j].x = (k0 + 0 < kmax) ? s[0] : 0.f;
                ebuf[j].y = (k0 + 1 < kmax) ? s[1] : 0.f;
                ebuf[j].z = (k0 + 2 < kmax) ? s[2] : 0.f;
                ebuf[j].w = (k0 + 3 < kmax) ? s[3] : 0.f;
            }
#pragma unroll
            for (int j = 0; j < 4; j++) {
                const float* s = a_base + aoff_o + (uint32_t)j * 32u * KDIM + koff;
                int k0 = koff + go * 2;
                obuf[j].x = (k0 + 0 < kmax) ? s[0] : 0.f;
                obuf[j].y = (k0 + 1 < kmax) ? s[1] : 0.f;
            }
        }
    };

    auto convert_stage = [&](uint32_t dstoff) {   // dstoff = SMEM_A16(d), compile-time in unroll
        char* a16 = smem + dstoff;
#pragma unroll
        for (int j = 0; j < 2; j++) {
            uint2 p = make_uint2(pack_h2(ebuf[j].y, ebuf[j].x), pack_h2(ebuf[j].w, ebuf[j].z));
            *reinterpret_cast<uint2*>(a16 + d16_e + (uint32_t)(j * 64 * RSH * 2)) = p;
        }
#pragma unroll
        for (int j = 0; j < 4; j++)
            *reinterpret_cast<uint32_t*>(a16 + d16_o + (uint32_t)(j * 32 * RSH * 2)) =
                pack_h2(obuf[j].y, obuf[j].x);
    };

    auto load_b = [&](uint32_t bufoff, int koff) {  // bufoff = SMEM_B16(s)
        const uint32_t b16 = sb + bufoff;
#pragma unroll
        for (int j = 0; j < 2; j++)   // B padded/zero-filled -> always safe
            cp16(b16 + d_b + (uint32_t)(j * 64 * RSH * 2),
                 b_base + boff + (uint32_t)j * 64u * KPAD + koff);
        cp_commit();
    };

    // MMA over stage buffers (offsets compile-time in the unrolled loop)
    auto mma_block = [&](uint32_t a16off, uint32_t b16off) {
        const uint32_t a16 = a_lm + a16off;
        const uint32_t b16 = b_lm + b16off;
#pragma unroll
        for (int ks = 0; ks < 2; ks++) {
            uint32_t a[4][4], bf[2][4];
#pragma unroll
            for (int mi = 0; mi < 4; mi++)
                ldsm4(a[mi][0], a[mi][1], a[mi][2], a[mi][3],
                      a16 + (uint32_t)(mi * 16 * RSH * 2) + (uint32_t)(ks * 32));
#pragma unroll
            for (int nj = 0; nj < 2; nj++)
                ldsm4(bf[nj][0], bf[nj][1], bf[nj][2], bf[nj][3],
                      b16 + (uint32_t)(nj * 16 * RSH * 2) + (uint32_t)(ks * 32));
#pragma unroll
            for (int mi = 0; mi < 4; mi++) {
                mma_fp16(acc[mi][0], a[mi], bf[0][0], bf[0][2]);
                mma_fp16(acc[mi][1], a[mi], bf[0][1], bf[0][3]);
                mma_fp16(acc[mi][2], a[mi], bf[1][0], bf[1][2]);
                mma_fp16(acc[mi][3], a[mi], bf[1][1], bf[1][3]);
            }
        }
    };

    // prologue (identical to proven R12)
    ldg_stage(0);                // regs <- stage 0
    load_b(SMEM_B16(0), 0);
    load_b(SMEM_B16(1), BK);
    convert_stage(SMEM_A16(0));  // A16[0] <- stage 0 (regs now dead)
    ldg_stage(BK);               // regs <- stage 1
    cp_wait1();                  // B(0) resident

    // main loop, unroll-6. Per step i (regs hold stage i+1 at entry):
    //   barrier; convert i+1 (consume regs); refill regs with i+2 + load B i+2;
    //   MMA on stage i; wait B(i+1).
    int koff_base = 2 * BK;      // = (ib + 2) * BK
#define STEP(p)                                                                          \
    if (ib + (p) < iters) {                                                              \
        const int i_ = ib + (p);                                                         \
        __syncthreads();                                                                 \
        if (i_ + 1 < iters) convert_stage(SMEM_A16(((p) + 1) & 1));                      \
        if (i_ + 2 < iters) {                                                            \
            load_b(SMEM_B16(((p) + 2) % 3), koff_base + (p) * BK);                       \
            ldg_stage(koff_base + (p) * BK);   /* regs dead after convert -> refill */   \
        }                                                                                \
        mma_block(SMEM_A16((p) & 1), SMEM_B16((p) % 3));                                 \
        if (i_ + 1 < iters) {                                                            \
            if (i_ + 2 < iters) cp_wait1(); else cp_wait0();                             \
        }                                                                                \
    }

    for (int ib = 0; ib < iters; ib += 6) {
        STEP(0) STEP(1) STEP(2) STEP(3) STEP(4) STEP(5)
        koff_base += 6 * BK;
    }
#undef STEP

    // write this split's partial
    float* base = g_part + (size_t)split * MDIM * NDIM;
#pragma unroll
    for (int mi = 0; mi < 4; mi++) {
        int r0 = m0 + wm + mi * 16 + lr;
#pragma unroll
        for (int ni = 0; ni < 4; ni++) {
            int c0 = wc + ni * 8 + 2 * lk;
            *reinterpret_cast<float2*>(base + (size_t)r0 * NDIM + c0) =
                make_float2(acc[mi][ni][0], acc[mi][ni][1]);
            *reinterpret_cast<float2*>(base + (size_t)(r0 + 8) * NDIM + c0) =
                make_float2(acc[mi][ni][2], acc[mi][ni][3]);
        }
    }

    // fused reduction: last CTA for this tile sums all splits in fixed order (deterministic)
    __threadfence();
    __shared__ int s_last;
    __syncthreads();
    if (tid == 0) s_last = (atomicAdd(&g_cnt[tile], 1) == SPLITS - 1) ? 1 : 0;
    __syncthreads();
    if (s_last) {
        const size_t t4 = (size_t)m0 * NDIM / 4;
#pragma unroll
        for (int j = 0; j < 16; j++) {
            size_t idx = t4 + (size_t)tid + (size_t)j * NTHREADS;
            float4 a4 = __ldcg(reinterpret_cast<const float4*>(g_part) + idx);
#pragma unroll
            for (int s = 1; s < SPLITS; s++) {
                float4 v = __ldcg(reinterpret_cast<const float4*>(g_part) +
                                  (size_t)s * (MDIM * NDIM / 4) + idx);
                a4.x += v.x; a4.y += v.y; a4.z += v.z; a4.w += v.w;
            }
            reinterpret_cast<float4*>(out)[idx] = a4;
        }
    }
}

// ---------------- launch ----------------
extern "C" void kernel_launch(void* const* d_in, const int* in_sizes, int n_in,
                              void* d_out, int out_size) {
    const float* input = (const float*)d_in[0];
    const float* w2v   = (const float*)d_in[1];
    if (n_in >= 2 && in_sizes[0] == 50000 * 128) {  // defensive: identify by size
        input = (const float*)d_in[1];
        w2v   = (const float*)d_in[0];
    }
    cudaFuncSetAttribute(gemm_fp16, cudaFuncAttributeMaxDynamicSharedMemorySize, SMEM_TOTAL);

    prep_b<<<dim3(KPAD / 32, NDIM / 32), dim3(32, 8)>>>(w2v);
    gemm_fp16<<<dim3(MDIM / BM, SPLITS), NTHREADS, SMEM_TOTAL>>>((float*)d_out, input);
}

// round 15
// speedup vs baseline: 1.0176x; 1.0176x over previous
#include <cuda_runtime.h>
#include <cuda_fp16.h>
#include <cstdint>

// out(4096,128) = input(4096,49998) @ word2vecs[0:49998](49998,128), fp32.
// fp16 m16n8k16 mma.sync path (same 11-bit significand as tf32 -> same error;
// tcgen05 unavailable: harness PTX target is compute_103, no 'a' features).
#define KDIM 49998
#define MDIM 4096
#define NDIM 128
#define KPAD 50048             // BT row stride in halves (zero-padded)
#define SPLITS 9
#define KSPLIT 5568            // 174*32 ; 9*5568 >= KDIM
#define BM 128
#define BK 32
#define NTHREADS 256
#define RSH 40                 // fp16 smem row stride (halves); 80B = 16B-mult
#define B16_BYTES (BM * RSH * 2)            // 10240
#define A16_BYTES (BM * RSH * 2)            // 10240
#define SMEM_B16(s) ((s) * B16_BYTES)                    // 4-ring: 0 .. 40960
#define SMEM_A16(d) (4 * B16_BYTES + (d) * A16_BYTES)    // 40960 ..
#define SMEM_TOTAL  (SMEM_A16(2))                        // 61440 -> 2 CTAs/SM (reg-capped)

__device__ __half g_bt16[(size_t)NDIM * KPAD];           // B^T fp16, zero-padded
__device__ float  g_part[(size_t)SPLITS * MDIM * NDIM];  // split-K partials
__device__ int    g_cnt[MDIM / BM];                      // per-tile arrival counters

// ---------------- helpers ----------------
__device__ __forceinline__ uint32_t smem_u32(const void* p) {
    uint32_t a;
    asm("{ .reg .u64 t; cvta.to.shared.u64 t, %1; cvt.u32.u64 %0, t; }" : "=r"(a) : "l"(p));
    return a;
}
__device__ __forceinline__ void cp16(uint32_t dst, const void* src) {
    asm volatile("cp.async.cg.shared.global [%0], [%1], 16;" :: "r"(dst), "l"(src));
}
__device__ __forceinline__ void cp_commit() { asm volatile("cp.async.commit_group;" ::: "memory"); }
__device__ __forceinline__ void cp_wait2() { asm volatile("cp.async.wait_group 2;" ::: "memory"); }
__device__ __forceinline__ void cp_wait1() { asm volatile("cp.async.wait_group 1;" ::: "memory"); }
__device__ __forceinline__ void cp_wait0() { asm volatile("cp.async.wait_group 0;" ::: "memory"); }

__device__ __forceinline__ uint32_t pack_h2(float hi, float lo) {
    uint32_t d;
    asm("cvt.rn.f16x2.f32 %0, %1, %2;" : "=r"(d) : "f"(hi), "f"(lo));
    return d;
}
__device__ __forceinline__ void ldsm4(uint32_t& r0, uint32_t& r1, uint32_t& r2, uint32_t& r3,
                                      uint32_t addr) {
    asm volatile("ldmatrix.sync.aligned.m8n8.x4.shared.b16 {%0,%1,%2,%3}, [%4];"
                 : "=r"(r0), "=r"(r1), "=r"(r2), "=r"(r3) : "r"(addr));
}
__device__ __forceinline__ void mma_fp16(float* c, const uint32_t* a, uint32_t b0, uint32_t b1) {
    asm volatile(
        "mma.sync.aligned.m16n8k16.row.col.f32.f16.f16.f32 "
        "{%0,%1,%2,%3}, {%4,%5,%6,%7}, {%8,%9}, {%0,%1,%2,%3};"
        : "+f"(c[0]), "+f"(c[1]), "+f"(c[2]), "+f"(c[3])
        : "r"(a[0]), "r"(a[1]), "r"(a[2]), "r"(a[3]), "r"(b0), "r"(b1));
}

// ------- kernel 1: transpose + fp16-convert B -> g_bt16[n][k] zero-padded; reset counters -------
__global__ void prep_b(const float* __restrict__ w2v) {
    __shared__ float tile[32][33];
    int k0 = blockIdx.x * 32;
    int n0 = blockIdx.y * 32;
    int tx = threadIdx.x, ty = threadIdx.y;  // 32 x 8
#pragma unroll
    for (int i = 0; i < 32; i += 8) {
        int k = k0 + ty + i;
        float v = 0.f;
        if (k < KDIM) v = w2v[(size_t)k * NDIM + n0 + tx];
        tile[ty + i][tx] = v;
    }
    __syncthreads();
#pragma unroll
    for (int i = 0; i < 32; i += 8) {
        int n = n0 + ty + i;
        g_bt16[(size_t)n * KPAD + k0 + tx] = __float2half_rn(tile[tx][ty + i]);
    }
    if (blockIdx.x == 0 && blockIdx.y == 0) {
        int tid = ty * 32 + tx;
        if (tid < MDIM / BM) g_cnt[tid] = 0;
    }
}

// ------- kernel 2: fp16 mma.sync GEMM; A LDG->reg->cvt->STS; B 4-ring; unroll-4 -------
__global__ void __launch_bounds__(NTHREADS, 2) gemm_fp16(float* __restrict__ out,
                                                         const float* __restrict__ A) {
    extern __shared__ char smem[];
    const uint32_t sb = smem_u32(smem);
    const int tid = threadIdx.x;
    const int wid = tid >> 5, lane = tid & 31;
    const int lr = lane >> 2, lk = lane & 3;

    const int tile = blockIdx.x;
    const int m0 = tile * BM;
    const int split = blockIdx.y;
    const int klo = split * KSPLIT;
    const int khi = min(KDIM, klo + KSPLIT);
    const int iters = (khi - klo + BK - 1) / BK;   // 174 (171 on last split)

    const int wm = (wid & 1) * 64;   // warp M offset
    const int wc = (wid >> 1) * 32;  // warp N offset

    const uint32_t lm_off = ((uint32_t)(lane & 15) * RSH + (uint32_t)((lane >> 4) << 3)) * 2u;
    const uint32_t a_lm = sb + lm_off + (uint32_t)(wm * RSH * 2);  // + SMEM_A16(d)
    const uint32_t b_lm = sb + lm_off + (uint32_t)(wc * RSH * 2);  // + SMEM_B16(s)

    // ---- per-thread A slots (LDG direct; same thread converts what it loads) ----
    const float* a_base = A + (size_t)m0 * KDIM + klo;
    const int re = 2 * (tid >> 3), ge = tid & 7;                 // even rows: float4
    const uint32_t aoff_e = (uint32_t)re * KDIM + (uint32_t)ge * 4;
    const uint32_t d16_e = (uint32_t)(re * RSH + ge * 4) * 2u;
    const int ro = 2 * (tid >> 4) + 1, go = tid & 15;            // odd rows: float2
    const uint32_t aoff_o = (uint32_t)ro * KDIM + (uint32_t)go * 2;
    const uint32_t d16_o = (uint32_t)(ro * RSH + go * 2) * 2u;
    // B cp16 slots
    const int nb = tid >> 2, gb = tid & 3;
    const uint32_t boff = (uint32_t)nb * KPAD + (uint32_t)gb * 8;
    const uint32_t d_b = (uint32_t)(nb * RSH + gb * 8) * 2u;
    const __half* b_base = g_bt16 + klo;

    float4 ebuf[2];
    float2 obuf[4];

    float acc[4][4][4];
#pragma unroll
    for (int mi = 0; mi < 4; mi++)
#pragma unroll
        for (int ni = 0; ni < 4; ni++)
#pragma unroll
            for (int q = 0; q < 4; q++) acc[mi][ni][q] = 0.f;

    auto ldg_stage = [&](int koff) {
        if (klo + koff + BK <= khi) {
#pragma unroll
            for (int j = 0; j < 2; j++)
                ebuf[j] = __ldcs(reinterpret_cast<const float4*>(a_base + aoff_e + (uint32_t)j * 64u * KDIM + koff));
#pragma unroll
            for (int j = 0; j < 4; j++)
                obuf[j] = __ldcs(reinterpret_cast<const float2*>(a_base + aoff_o + (uint32_t)j * 32u * KDIM + koff));
        } else {
            const int kmax = khi - klo;
#pragma unroll
            for (int j = 0; j < 2; j++) {
                const float* s = a_base + aoff_e + (uint32_t)j * 64u * KDIM + koff;
                int k0 = koff + ge * 4;
                ebuf[j].x = (k0 + 0 < kmax) ? s[0] : 0.f;
                ebuf[j].y = (k0 + 1 < kmax) ? s[1] : 0.f;
                ebuf[j].z = (k0 + 2 < kmax) ? s[2] : 0.f;
                ebuf[j].w = (k0 + 3 < kmax) ? s[3] : 0.f;
            }
#pragma unroll
            for (int j = 0; j < 4; j++) {
                const float* s = a_base + aoff_o + (uint32_t)j * 32u * KDIM + koff;
                int k0 = koff + go * 2;
                obuf[j].x = (k0 + 0 < kmax) ? s[0] : 0.f;
                obuf[j].y = (k0 + 1 < kmax) ? s[1] : 0.f;
            }
        }
    };

    auto convert_stage = [&](uint32_t dstoff) {   // dstoff = SMEM_A16(d), compile-time in unroll
        char* a16 = smem + dstoff;
#pragma unroll
        for (int j = 0; j < 2; j++) {
            uint2 p = make_uint2(pack_h2(ebuf[j].y, ebuf[j].x), pack_h2(ebuf[j].w, ebuf[j].z));
            *reinterpret_cast<uint2*>(a16 + d16_e + (uint32_t)(j * 64 * RSH * 2)) = p;
        }
#pragma unroll
        for (int j = 0; j < 4; j++)
            *reinterpret_cast<uint32_t*>(a16 + d16_o + (uint32_t)(j * 32 * RSH * 2)) =
                pack_h2(obuf[j].y, obuf[j].x);
    };

    auto load_b = [&](uint32_t bufoff, int koff) {  // bufoff = SMEM_B16(s)
        const uint32_t b16 = sb + bufoff;
#pragma unroll
        for (int j = 0; j < 2; j++)   // B padded/zero-filled -> always safe
            cp16(b16 + d_b + (uint32_t)(j * 64 * RSH * 2),
                 b_base + boff + (uint32_t)j * 64u * KPAD + koff);
        cp_commit();
    };

    // MMA over stage buffers (offsets compile-time in the unrolled loop)
    auto mma_block = [&](uint32_t a16off, uint32_t b16off) {
        const uint32_t a16 = a_lm + a16off;
        const uint32_t b16 = b_lm + b16off;
#pragma unroll
        for (int ks = 0; ks < 2; ks++) {
            uint32_t a[4][4], bf[2][4];
#pragma unroll
            for (int nj = 0; nj < 2; nj++)   // B first: needed by every mi group
                ldsm4(bf[nj][0], bf[nj][1], bf[nj][2], bf[nj][3],
                      b16 + (uint32_t)(nj * 16 * RSH * 2) + (uint32_t)(ks * 32));
#pragma unroll
            for (int mi = 0; mi < 4; mi++)
                ldsm4(a[mi][0], a[mi][1], a[mi][2], a[mi][3],
                      a16 + (uint32_t)(mi * 16 * RSH * 2) + (uint32_t)(ks * 32));
#pragma unroll
            for (int mi = 0; mi < 4; mi++) {
                mma_fp16(acc[mi][0], a[mi], bf[0][0], bf[0][2]);
                mma_fp16(acc[mi][1], a[mi], bf[0][1], bf[0][3]);
                mma_fp16(acc[mi][2], a[mi], bf[1][0], bf[1][2]);
                mma_fp16(acc[mi][3], a[mi], bf[1][1], bf[1][3]);
            }
        }
    };

    // prologue: B 3 stages ahead; regs hold stage 1; A16[0] converted
    ldg_stage(0);
    load_b(SMEM_B16(0), 0);
    load_b(SMEM_B16(1), BK);
    load_b(SMEM_B16(2), 2 * BK);
    convert_stage(SMEM_A16(0));
    ldg_stage(BK);
    cp_wait2();                  // B(0) resident

    // main loop, unroll-4 (lcm of B ring-4 and A16 double buffer).
    // Invariant at top of step i: regs=A(i+1), A16[i&1] ready, B(i) resident.
    int koff_base = 2 * BK;      // = (ib + 2) * BK
#define STEP(p)                                                                          \
    if (ib + (p) < iters) {                                                              \
        const int i_ = ib + (p);                                                         \
        __syncthreads();                                                                 \
        if (i_ + 3 < iters) load_b(SMEM_B16(((p) + 3) & 3), koff_base + ((p) + 1) * BK); \
        mma_block(SMEM_A16((p) & 1), SMEM_B16((p) & 3));                                 \
        if (i_ + 1 < iters) {                                                            \
            convert_stage(SMEM_A16(((p) + 1) & 1));                                      \
            if (i_ + 2 < iters) ldg_stage(koff_base + (p) * BK);                         \
            if (i_ + 3 < iters)      cp_wait2();                                         \
            else if (i_ + 2 < iters) cp_wait1();                                         \
            else                     cp_wait0();                                         \
        }                                                                                \
    }

    for (int ib = 0; ib < iters; ib += 4) {
        STEP(0) STEP(1) STEP(2) STEP(3)
        koff_base += 4 * BK;
    }
#undef STEP

    // write this split's partial
    float* base = g_part + (size_t)split * MDIM * NDIM;
#pragma unroll
    for (int mi = 0; mi < 4; mi++) {
        int r0 = m0 + wm + mi * 16 + lr;
#pragma unroll
        for (int ni = 0; ni < 4; ni++) {
            int c0 = wc + ni * 8 + 2 * lk;
            *reinterpret_cast<float2*>(base + (size_t)r0 * NDIM + c0) =
                make_float2(acc[mi][ni][0], acc[mi][ni][1]);
            *reinterpret_cast<float2*>(base + (size_t)(r0 + 8) * NDIM + c0) =
                make_float2(acc[mi][ni][2], acc[mi][ni][3]);
        }
    }

    // fused reduction: last CTA for this tile sums all splits in fixed order (deterministic)
    __threadfence();
    __shared__ int s_last;
    __syncthreads();
    if (tid == 0) s_last = (atomicAdd(&g_cnt[tile], 1) == SPLITS - 1) ? 1 : 0;
    __syncthreads();
    if (s_last) {
        const size_t t4 = (size_t)m0 * NDIM / 4;
#pragma unroll
        for (int j = 0; j < 16; j++) {
            size_t idx = t4 + (size_t)tid + (size_t)j * NTHREADS;
            float4 a4 = __ldcg(reinterpret_cast<const float4*>(g_part) + idx);
#pragma unroll
            for (int s = 1; s < SPLITS; s++) {
                float4 v = __ldcg(reinterpret_cast<const float4*>(g_part) +
                                  (size_t)s * (MDIM * NDIM / 4) + idx);
                a4.x += v.x; a4.y += v.y; a4.z += v.z; a4.w += v.w;
            }
            reinterpret_cast<float4*>(out)[idx] = a4;
        }
    }
}

// ---------------- launch ----------------
extern "C" void kernel_launch(void* const* d_in, const int* in_sizes, int n_in,
                              void* d_out, int out_size) {
    const float* input = (const float*)d_in[0];
    const float* w2v   = (const float*)d_in[1];
    if (n_in >= 2 && in_sizes[0] == 50000 * 128) {  // defensive: identify by size
        input = (const float*)d_in[1];
        w2v   = (const float*)d_in[0];
    }
    cudaFuncSetAttribute(gemm_fp16, cudaFuncAttributeMaxDynamicSharedMemorySize, SMEM_TOTAL);

    prep_b<<<dim3(KPAD / 32, NDIM / 32), dim3(32, 8)>>>(w2v);
    gemm_fp16<<<dim3(MDIM / BM, SPLITS), NTHREADS, SMEM_TOTAL>>>((float*)d_out, input);
}